// round 9
// baseline (speedup 1.0000x reference)
#include <cuda_runtime.h>
#include <math_constants.h>

#define SEGS_PER_BLOCK 4

// ---------------------------------------------------------------------------
// Single-thread galloping lower_bound on the sorted id array, starting from a
// uniform-distribution guess. ~3 gallop + ~8 binary probes, all L2-hot.
// Returns first index i with (int)s[i] >= t.
// ---------------------------------------------------------------------------
template <typename T>
__device__ __forceinline__ int gallop_lb(const T* __restrict__ s, int n,
                                         int t, int guess) {
    int lo, hi;
    if ((int)__ldg(&s[guess]) >= t) {          // answer <= guess
        int step = 64;
        hi = guess;                             // s[hi] >= t
        int probe = guess - step;
        while (probe >= 0 && (int)__ldg(&s[probe]) >= t) {
            hi = probe; step <<= 1; probe = guess - step;
        }
        lo = (probe < 0) ? 0 : probe + 1;       // s[probe] < t (or begin)
    } else {                                    // answer > guess
        int step = 64;
        lo = guess + 1;                         // s[guess] < t
        int probe = guess + step;
        while (probe < n && (int)__ldg(&s[probe]) < t) {
            lo = probe + 1; step <<= 1; probe = guess + step;
        }
        hi = (probe >= n) ? n : probe;          // s[hi] >= t (or end)
    }
    while (lo < hi) {
        int mid = (lo + hi) >> 1;
        if ((int)__ldg(&s[mid]) < t) lo = mid + 1; else hi = mid;
    }
    return lo;
}

// ---------------------------------------------------------------------------
// Single fused kernel, no global sync. Block b owns segments
// [4b, 4b+4). Warp-0 lanes 0..SEGS_PER_BLOCK concurrently resolve the 5
// segment bounds via galloping scalar search (one chain latency for all 5,
// ~10 L2-hot probes). Then the block streams its ~contiguous row range one
// segment at a time with the measured-best R2 loop: 4 row-groups x 32 lanes,
// lane l owns features [4l,4l+4) via float4 streaming loads; cross-group
// combine in smem; thread (stat,lane) writes one float4 streaming store.
// Handles int64 (reference dtype) and int32 (JAX default) via dtype sniff.
// ---------------------------------------------------------------------------
__global__ void __launch_bounds__(128, 12)
seg_pool_kernel(const float* __restrict__ x, const void* __restrict__ seg,
                float* __restrict__ out, int n, int G) {
    const int tid  = threadIdx.x;
    const int lane = tid & 31;
    const int grp  = tid >> 5;
    const int g0   = blockIdx.x * SEGS_PER_BLOCK;

    __shared__ int sb[SEGS_PER_BLOCK + 1];

    if (tid <= SEGS_PER_BLOCK) {
        // dtype sniff: int64 word at index n/4 covers int32 elements n/2,
        // n/2+1. Sorted ids: middle element ~G/2 != 0, so int32 data read as
        // int64 is >= 2^32; genuine int64 data stays a small id.
        const long long probe = ((const long long*)seg)[n >> 2];
        const bool is64 = (probe >= 0) && (probe < (1LL << 31));

        const int t = g0 + tid;
        int lb;
        if (t <= 0)       lb = 0;
        else if (t >= G)  lb = n;
        else {
            int guess = (int)(((long long)t * (long long)n) / (long long)G);
            if (guess > n - 1) guess = n - 1;
            if (guess < 0) guess = 0;
            lb = is64 ? gallop_lb((const long long*)seg, n, t, guess)
                      : gallop_lb((const int*)seg,       n, t, guess);
        }
        sb[tid] = lb;
    }
    __syncthreads();

    const float4* __restrict__ xv = (const float4*)x;  // row stride = 32 float4
    __shared__ float4 sm4[4][4][32];  // [stat][group][lane], 8 KB

    #pragma unroll 1
    for (int j = 0; j < SEGS_PER_BLOCK; j++) {
        const int g = g0 + j;
        if (g >= G) break;
        const int start = sb[j];
        const int end   = sb[j + 1];

        float4 s  = make_float4(0.f, 0.f, 0.f, 0.f);
        float4 q  = make_float4(0.f, 0.f, 0.f, 0.f);
        float4 mx = make_float4(-CUDART_INF_F, -CUDART_INF_F, -CUDART_INF_F, -CUDART_INF_F);
        float4 mn = make_float4( CUDART_INF_F,  CUDART_INF_F,  CUDART_INF_F,  CUDART_INF_F);

        #pragma unroll 4
        for (int r = start + grp; r < end; r += 4) {
            float4 v = __ldcs(&xv[(size_t)r * 32 + lane]);
            s.x += v.x; s.y += v.y; s.z += v.z; s.w += v.w;
            q.x = fmaf(v.x, v.x, q.x); q.y = fmaf(v.y, v.y, q.y);
            q.z = fmaf(v.z, v.z, q.z); q.w = fmaf(v.w, v.w, q.w);
            mx.x = fmaxf(mx.x, v.x); mx.y = fmaxf(mx.y, v.y);
            mx.z = fmaxf(mx.z, v.z); mx.w = fmaxf(mx.w, v.w);
            mn.x = fminf(mn.x, v.x); mn.y = fminf(mn.y, v.y);
            mn.z = fminf(mn.z, v.z); mn.w = fminf(mn.w, v.w);
        }

        // stat order = output order: 0=max, 1=min, 2=sum(->mean), 3=sumsq(->std)
        sm4[0][grp][lane] = mx;
        sm4[1][grp][lane] = mn;
        sm4[2][grp][lane] = s;
        sm4[3][grp][lane] = q;
        __syncthreads();

        // epilogue: thread (stat st=grp, lane l) combines the 4 group partials
        const int st = grp;
        const int l  = lane;
        const float cnt = (float)(end - start);

        float4 r = sm4[st][0][l];
        if (st == 0) {
            #pragma unroll
            for (int k = 1; k < 4; k++) {
                float4 t4 = sm4[0][k][l];
                r.x = fmaxf(r.x, t4.x); r.y = fmaxf(r.y, t4.y);
                r.z = fmaxf(r.z, t4.z); r.w = fmaxf(r.w, t4.w);
            }
        } else if (st == 1) {
            #pragma unroll
            for (int k = 1; k < 4; k++) {
                float4 t4 = sm4[1][k][l];
                r.x = fminf(r.x, t4.x); r.y = fminf(r.y, t4.y);
                r.z = fminf(r.z, t4.z); r.w = fminf(r.w, t4.w);
            }
        } else if (st == 2) {
            #pragma unroll
            for (int k = 1; k < 4; k++) {
                float4 t4 = sm4[2][k][l];
                r.x += t4.x; r.y += t4.y; r.z += t4.z; r.w += t4.w;
            }
            r.x /= cnt; r.y /= cnt; r.z /= cnt; r.w /= cnt;  // mean
        } else {
            float4 su = sm4[2][0][l];
            #pragma unroll
            for (int k = 1; k < 4; k++) {
                float4 tq = sm4[3][k][l];
                float4 ts = sm4[2][k][l];
                r.x += tq.x; r.y += tq.y; r.z += tq.z; r.w += tq.w;
                su.x += ts.x; su.y += ts.y; su.z += ts.z; su.w += ts.w;
            }
            const float inv = 1.0f / cnt;
            const float ax = su.x * inv, ay = su.y * inv,
                        az = su.z * inv, aw = su.w * inv;
            const float d = cnt - 1.0f;
            r.x = sqrtf(fmaxf((r.x - cnt * ax * ax) / d, 0.0f));
            r.y = sqrtf(fmaxf((r.y - cnt * ay * ay) / d, 0.0f));
            r.z = sqrtf(fmaxf((r.z - cnt * az * az) / d, 0.0f));
            r.w = sqrtf(fmaxf((r.w - cnt * aw * aw) / d, 0.0f));
        }

        // out[g][st][4l .. 4l+4): one coalesced 16B streaming store
        float4* o4 = (float4*)(out + (size_t)g * 512 + st * 128);
        __stcs(&o4[l], r);

        __syncthreads();  // sm4 reused by next segment
    }
}

extern "C" void kernel_launch(void* const* d_in, const int* in_sizes, int n_in,
                              void* d_out, int out_size) {
    const float* x   = (const float*)d_in[0];
    const void*  seg = d_in[1];
    float* out = (float*)d_out;

    const int D = 128;
    const int n = in_sizes[0] / D;          // number of rows
    const int G = out_size / (4 * D);       // number of segments

    const int nb = (G + SEGS_PER_BLOCK - 1) / SEGS_PER_BLOCK;
    seg_pool_kernel<<<nb, 128>>>(x, seg, out, n, G);
}

// round 10
// speedup vs baseline: 1.0785x; 1.0785x over previous
#include <cuda_runtime.h>
#include <math_constants.h>

// ---------------------------------------------------------------------------
// Single-thread galloping lower_bound on the sorted id array, starting from a
// uniform-distribution guess. ~4 gallop + ~10 binary probes, L2-hot after
// wave 1. Returns first index i with (int)s[i] >= t.
// ---------------------------------------------------------------------------
template <typename T>
__device__ __forceinline__ int gallop_lb(const T* __restrict__ s, int n,
                                         int t, int guess) {
    int lo, hi;
    if ((int)__ldg(&s[guess]) >= t) {          // answer <= guess
        int step = 64;
        hi = guess;                             // s[hi] >= t
        int probe = guess - step;
        while (probe >= 0 && (int)__ldg(&s[probe]) >= t) {
            hi = probe; step <<= 1; probe = guess - step;
        }
        lo = (probe < 0) ? 0 : probe + 1;       // s[probe] < t (or begin)
    } else {                                    // answer > guess
        int step = 64;
        lo = guess + 1;                         // s[guess] < t
        int probe = guess + step;
        while (probe < n && (int)__ldg(&s[probe]) < t) {
            lo = probe + 1; step <<= 1; probe = guess + step;
        }
        hi = (probe >= n) ? n : probe;          // s[hi] >= t (or end)
    }
    while (lo < hi) {
        int mid = (lo + hi) >> 1;
        if ((int)__ldg(&s[mid]) < t) lo = mid + 1; else hi = mid;
    }
    return lo;
}

// ---------------------------------------------------------------------------
// Single kernel, ONE SEGMENT PER BLOCK (the measured-best R2 block shape),
// no second launch, no global sync. Lanes 0-1 of warp 0 resolve the segment's
// [start, end) via concurrent scalar gallop searches (~14 L2-hot probes in
// one SIMT chain, ~1.6us, hidden behind the other resident blocks' streams).
// Then the unmodified R2 streaming loop: 4 row-groups x 32 lanes, lane l owns
// features [4l,4l+4) via float4 streaming loads; cross-group combine in smem;
// thread (stat,lane) writes one float4 streaming store.
// Handles int64 (reference dtype) and int32 (JAX default) via dtype sniff.
// ---------------------------------------------------------------------------
__global__ void __launch_bounds__(128, 12)
seg_pool_kernel(const float* __restrict__ x, const void* __restrict__ seg,
                float* __restrict__ out, int n, int G) {
    const int tid  = threadIdx.x;
    const int lane = tid & 31;
    const int grp  = tid >> 5;
    const int g    = blockIdx.x;

    __shared__ int sb[2];

    if (tid < 2) {
        // dtype sniff: int64 word at index n/4 covers int32 elements n/2,
        // n/2+1. Sorted ids: middle element ~G/2 != 0, so int32 data read as
        // int64 is >= 2^32; genuine int64 data stays a small id.
        const long long probe = ((const long long*)seg)[n >> 2];
        const bool is64 = (probe >= 0) && (probe < (1LL << 31));

        const int t = g + tid;     // lane0: lb(g)=start, lane1: lb(g+1)=end
        int lb;
        if (t <= 0)       lb = 0;
        else if (t >= G)  lb = n;
        else {
            int guess = (int)(((long long)t * (long long)n) / (long long)G);
            if (guess > n - 1) guess = n - 1;
            if (guess < 0) guess = 0;
            lb = is64 ? gallop_lb((const long long*)seg, n, t, guess)
                      : gallop_lb((const int*)seg,       n, t, guess);
        }
        sb[tid] = lb;
    }
    __syncthreads();

    const int start = sb[0];
    const int end   = sb[1];

    float4 s  = make_float4(0.f, 0.f, 0.f, 0.f);
    float4 q  = make_float4(0.f, 0.f, 0.f, 0.f);
    float4 mx = make_float4(-CUDART_INF_F, -CUDART_INF_F, -CUDART_INF_F, -CUDART_INF_F);
    float4 mn = make_float4( CUDART_INF_F,  CUDART_INF_F,  CUDART_INF_F,  CUDART_INF_F);

    const float4* __restrict__ xv = (const float4*)x;  // row stride = 32 float4

    #pragma unroll 4
    for (int r = start + grp; r < end; r += 4) {
        float4 v = __ldcs(&xv[(size_t)r * 32 + lane]);
        s.x += v.x; s.y += v.y; s.z += v.z; s.w += v.w;
        q.x = fmaf(v.x, v.x, q.x); q.y = fmaf(v.y, v.y, q.y);
        q.z = fmaf(v.z, v.z, q.z); q.w = fmaf(v.w, v.w, q.w);
        mx.x = fmaxf(mx.x, v.x); mx.y = fmaxf(mx.y, v.y);
        mx.z = fmaxf(mx.z, v.z); mx.w = fmaxf(mx.w, v.w);
        mn.x = fminf(mn.x, v.x); mn.y = fminf(mn.y, v.y);
        mn.z = fminf(mn.z, v.z); mn.w = fminf(mn.w, v.w);
    }

    // partials: [stat][group][lane] as float4 -> 8 KB
    // stat order = output order: 0=max, 1=min, 2=sum(->mean), 3=sumsq(->std)
    __shared__ float4 sm4[4][4][32];
    sm4[0][grp][lane] = mx;
    sm4[1][grp][lane] = mn;
    sm4[2][grp][lane] = s;
    sm4[3][grp][lane] = q;
    __syncthreads();

    // epilogue: thread (stat st=grp, lane l) combines the 4 group partials
    const int st = grp;
    const int l  = lane;
    const float cnt = (float)(end - start);

    float4 r = sm4[st][0][l];
    if (st == 0) {
        #pragma unroll
        for (int k = 1; k < 4; k++) {
            float4 t4 = sm4[0][k][l];
            r.x = fmaxf(r.x, t4.x); r.y = fmaxf(r.y, t4.y);
            r.z = fmaxf(r.z, t4.z); r.w = fmaxf(r.w, t4.w);
        }
    } else if (st == 1) {
        #pragma unroll
        for (int k = 1; k < 4; k++) {
            float4 t4 = sm4[1][k][l];
            r.x = fminf(r.x, t4.x); r.y = fminf(r.y, t4.y);
            r.z = fminf(r.z, t4.z); r.w = fminf(r.w, t4.w);
        }
    } else if (st == 2) {
        #pragma unroll
        for (int k = 1; k < 4; k++) {
            float4 t4 = sm4[2][k][l];
            r.x += t4.x; r.y += t4.y; r.z += t4.z; r.w += t4.w;
        }
        r.x /= cnt; r.y /= cnt; r.z /= cnt; r.w /= cnt;  // mean
    } else {
        float4 su = sm4[2][0][l];
        #pragma unroll
        for (int k = 1; k < 4; k++) {
            float4 tq = sm4[3][k][l];
            float4 ts = sm4[2][k][l];
            r.x += tq.x; r.y += tq.y; r.z += tq.z; r.w += tq.w;
            su.x += ts.x; su.y += ts.y; su.z += ts.z; su.w += ts.w;
        }
        const float inv = 1.0f / cnt;
        const float ax = su.x * inv, ay = su.y * inv,
                    az = su.z * inv, aw = su.w * inv;
        const float d = cnt - 1.0f;
        r.x = sqrtf(fmaxf((r.x - cnt * ax * ax) / d, 0.0f));
        r.y = sqrtf(fmaxf((r.y - cnt * ay * ay) / d, 0.0f));
        r.z = sqrtf(fmaxf((r.z - cnt * az * az) / d, 0.0f));
        r.w = sqrtf(fmaxf((r.w - cnt * aw * aw) / d, 0.0f));
    }

    // out[g][st][4l .. 4l+4): one coalesced 16B streaming store
    float4* o4 = (float4*)(out + (size_t)g * 512 + st * 128);
    __stcs(&o4[l], r);
}

extern "C" void kernel_launch(void* const* d_in, const int* in_sizes, int n_in,
                              void* d_out, int out_size) {
    const float* x   = (const float*)d_in[0];
    const void*  seg = d_in[1];
    float* out = (float*)d_out;

    const int D = 128;
    const int n = in_sizes[0] / D;          // number of rows
    const int G = out_size / (4 * D);       // number of segments

    seg_pool_kernel<<<G, 128>>>(x, seg, out, n, G);
}

// round 12
// speedup vs baseline: 1.1305x; 1.0481x over previous
#include <cuda_runtime.h>
#include <math_constants.h>

// Scratch for segment offsets (allocation-free rule: __device__ global).
__device__ int g_offsets[65537];

// ---------------------------------------------------------------------------
// Kernel 1: streaming boundary scan over the SORTED segment_ids array.
// Thread i reads seg[i] and seg[i+1]; at each transition it fills the
// offsets for every id in (seg[i], seg[i+1]]. Edge threads fill the head
// ([0, seg[0]]) and tail ((seg[n-1], G]). One coalesced pass (~2us).
// Handles both int64 (reference dtype) and int32 (JAX default) via sniffing.
// ---------------------------------------------------------------------------
__global__ void seg_boundaries_kernel(const void* __restrict__ seg, int n, int G) {
    const int i = blockIdx.x * blockDim.x + threadIdx.x;
    if (i >= n) return;

    // dtype sniff: int64 word at index n/4 covers int32 elements n/2, n/2+1.
    // Sorted ids: middle element ~G/2 != 0, so int32 data read as int64 is
    // >= 2^32; genuine int64 data stays a small id.
    const long long probe = ((const long long*)seg)[n >> 2];
    const bool is64 = (probe >= 0) && (probe < (1LL << 31));

    int id, next;
    if (is64) {
        const long long* s = (const long long*)seg;
        id   = (int)s[i];
        next = (i + 1 < n) ? (int)s[i + 1] : G;
    } else {
        const int* s = (const int*)seg;
        id   = s[i];
        next = (i + 1 < n) ? s[i + 1] : G;
    }

    if (i == 0) {
        for (int g = 0; g <= id; g++) g_offsets[g] = 0;
    }
    // first row of every segment in (id, next] is i+1
    for (int g = id + 1; g <= next; g++) g_offsets[g] = i + 1;
}

// ---------------------------------------------------------------------------
// Kernel 2 (measured-best configuration): one block per segment. 128 threads
// = 4 row-groups x 32 lanes. Lane l owns features [4l, 4l+4) via float4
// (coalesced LDG.128, streaming hint). Row-group r processes rows start+r,
// start+r+4, ... Cross-group combine in shared memory, then thread f writes
// the 4 stats for feature f.
// ---------------------------------------------------------------------------
__global__ void __launch_bounds__(128, 12)
seg_pool_kernel(const float* __restrict__ x, float* __restrict__ out, int G) {
    const int g = blockIdx.x;
    const int start = g_offsets[g];
    const int end   = g_offsets[g + 1];

    const int lane = threadIdx.x & 31;
    const int grp  = threadIdx.x >> 5;

    float4 s  = make_float4(0.f, 0.f, 0.f, 0.f);
    float4 q  = make_float4(0.f, 0.f, 0.f, 0.f);
    float4 mx = make_float4(-CUDART_INF_F, -CUDART_INF_F, -CUDART_INF_F, -CUDART_INF_F);
    float4 mn = make_float4( CUDART_INF_F,  CUDART_INF_F,  CUDART_INF_F,  CUDART_INF_F);

    const float4* __restrict__ xv = (const float4*)x;  // row stride = 32 float4

    #pragma unroll 4
    for (int r = start + grp; r < end; r += 4) {
        float4 v = __ldcs(&xv[(size_t)r * 32 + lane]);
        s.x += v.x; s.y += v.y; s.z += v.z; s.w += v.w;
        q.x = fmaf(v.x, v.x, q.x); q.y = fmaf(v.y, v.y, q.y);
        q.z = fmaf(v.z, v.z, q.z); q.w = fmaf(v.w, v.w, q.w);
        mx.x = fmaxf(mx.x, v.x); mx.y = fmaxf(mx.y, v.y);
        mx.z = fmaxf(mx.z, v.z); mx.w = fmaxf(mx.w, v.w);
        mn.x = fminf(mn.x, v.x); mn.y = fminf(mn.y, v.y);
        mn.z = fminf(mn.z, v.z); mn.w = fminf(mn.w, v.w);
    }

    // partials: [stat][group][lane] as float4 -> 4*4*32*16B = 8 KB
    __shared__ float4 sm4[4][4][32];
    sm4[0][grp][lane] = s;
    sm4[1][grp][lane] = q;
    sm4[2][grp][lane] = mx;
    sm4[3][grp][lane] = mn;
    __syncthreads();

    // thread f in [0,128) combines the 4 group partials for feature f
    const int f = threadIdx.x;
    float sum = 0.f, sq = 0.f;
    float M = -CUDART_INF_F, m = CUDART_INF_F;
    #pragma unroll
    for (int k = 0; k < 4; k++) {
        const float* p0 = (const float*)&sm4[0][k][0];
        const float* p1 = (const float*)&sm4[1][k][0];
        const float* p2 = (const float*)&sm4[2][k][0];
        const float* p3 = (const float*)&sm4[3][k][0];
        sum += p0[f];
        sq  += p1[f];
        M = fmaxf(M, p2[f]);
        m = fminf(m, p3[f]);
    }

    const float cnt  = (float)(end - start);
    const float mean = sum / cnt;
    const float var  = (sq - cnt * mean * mean) / (cnt - 1.0f);
    const float sd   = sqrtf(fmaxf(var, 0.0f));

    float* o = out + (size_t)g * 512;  // [4][128] per segment
    o[f]        = M;
    o[128 + f]  = m;
    o[256 + f]  = mean;
    o[384 + f]  = sd;
}

extern "C" void kernel_launch(void* const* d_in, const int* in_sizes, int n_in,
                              void* d_out, int out_size) {
    const float* x   = (const float*)d_in[0];
    const void*  seg = d_in[1];
    float* out = (float*)d_out;

    const int D = 128;
    const int n = in_sizes[0] / D;          // number of rows
    const int G = out_size / (4 * D);       // number of segments

    int tb = 256;
    int nb = (n + tb - 1) / tb;
    seg_boundaries_kernel<<<nb, tb>>>(seg, n, G);
    seg_pool_kernel<<<G, 128>>>(x, out, G);
}